// round 14
// baseline (speedup 1.0000x reference)
#include <cuda_runtime.h>
#include <cuda_fp16.h>
#include <math.h>
#include <stdint.h>

#define NN 50000
#define EE 800000
#define KDIM 128
#define HID 128
#define CLS 40

#define ALD 68   // half2-words per smem row (64 data + 4 pad) -> conflict-free MMA frag loads

// ---------------- scratch (device globals; no allocation allowed) ----------------
__device__ int   g_deg_out[NN];
__device__ int   g_deg_in[NN];
__device__ int   g_cursor[NN];
__device__ int   g_row_ptr[NN + 1];
__device__ int   g_col[EE];
__device__ float g_norm_out[NN];
__device__ float g_norm_in[NN];
__device__ int   g_block_sums[256];
__device__ unsigned g_bar_arrive;
__device__ unsigned g_bar_release;
__device__ __align__(16) uint32_t g_wt0[128 * ALD];
__device__ __align__(16) uint32_t g_wt1[128 * ALD];
__device__ __align__(16) uint32_t g_wt2[40 * ALD];
__device__ __align__(16) uint32_t g_buf_a[(size_t)NN * 64];   // fp16, 64 words/row
__device__ __align__(16) uint32_t g_buf_b[(size_t)NN * 64];

// ---------------- graph preprocessing ----------------
__global__ void init_zero_kernel(int n) {
    for (int i = blockIdx.x * blockDim.x + threadIdx.x; i < n; i += gridDim.x * blockDim.x) {
        g_deg_out[i] = 0;
        g_deg_in[i]  = 0;
    }
}

__global__ void degree_kernel(const int* __restrict__ src, const int* __restrict__ dst, int E) {
    int e = blockIdx.x * blockDim.x + threadIdx.x;
    if (e < E) {
        atomicAdd(&g_deg_out[src[e]], 1);
        atomicAdd(&g_deg_in[dst[e]], 1);
    }
}

// fused: per-node norms + per-block partial sums of deg_in
__global__ void norm_partial_kernel(int n) {
    __shared__ int sdata[8];
    int t = threadIdx.x;
    int i = blockIdx.x * 256 + t;
    int din = 0;
    if (i < n) {
        int dout = g_deg_out[i]; if (dout < 1) dout = 1;
        din = g_deg_in[i];
        int dc = (din < 1) ? 1 : din;
        g_norm_out[i] = rsqrtf((float)dout);
        g_norm_in[i]  = rsqrtf((float)dc);
    }
    int v = din;
    for (int off = 16; off > 0; off >>= 1)
        v += __shfl_down_sync(0xffffffff, v, off);
    if ((t & 31) == 0) sdata[t >> 5] = v;
    __syncthreads();
    if (t < 8) {
        int w = sdata[t];
        for (int off = 4; off > 0; off >>= 1)
            w += __shfl_down_sync(0xff, w, off);
        if (t == 0) g_block_sums[blockIdx.x] = w;
    }
}

// fill row_ptr + cursor; each block redundantly scans the <=256 block partials.
// Also resets the layers_kernel grid-barrier counters (runs every replay, before layers).
__global__ void fill_rowptr_kernel(int nblocks, int n) {
    __shared__ int sg[256];
    __shared__ int sl[256];
    int t = threadIdx.x;
    if (blockIdx.x == 0 && t == 0) {
        g_bar_arrive  = 0u;
        g_bar_release = 0u;
    }
    int v = (t < nblocks) ? g_block_sums[t] : 0;
    sg[t] = v;
    __syncthreads();
    for (int off = 1; off < 256; off <<= 1) {
        int u = (t >= off) ? sg[t - off] : 0;
        __syncthreads();
        sg[t] += u;
        __syncthreads();
    }
    int blockOff = (blockIdx.x == 0) ? 0 : sg[blockIdx.x - 1];
    if (blockIdx.x == 0 && t == 0) g_row_ptr[n] = sg[nblocks - 1];
    int i = blockIdx.x * 256 + t;
    int d = (i < n) ? g_deg_in[i] : 0;
    sl[t] = d;
    __syncthreads();
    for (int off = 1; off < 256; off <<= 1) {
        int u = (t >= off) ? sl[t - off] : 0;
        __syncthreads();
        sl[t] += u;
        __syncthreads();
    }
    if (i < n) {
        int rp = sl[t] - d + blockOff;
        g_row_ptr[i] = rp;
        g_cursor[i]  = rp;
    }
}

__global__ void csr_fill_kernel(const int* __restrict__ src, const int* __restrict__ dst, int E) {
    int e = blockIdx.x * blockDim.x + threadIdx.x;
    if (e < E) {
        int p = atomicAdd(&g_cursor[dst[e]], 1);
        g_col[p] = src[e];
    }
}

// ---------------- fused weight pre-conversion (all three) ----------------
__global__ void wconvert_all_kernel(const float* __restrict__ W0, const float* __restrict__ W1,
                                    const float* __restrict__ W2) {
    int li = blockIdx.x * 256 + threadIdx.x;
    if (li < 8192) {
        int n = li & 127, j = li >> 7;
        __half2 h = __float22half2_rn(make_float2(W0[(size_t)(2 * j) * 128 + n],
                                                  W0[(size_t)(2 * j + 1) * 128 + n]));
        g_wt0[n * ALD + j] = *(uint32_t*)&h;
    } else if (li < 16384) {
        int t2 = li - 8192;
        int n = t2 & 127, j = t2 >> 7;
        __half2 h = __float22half2_rn(make_float2(W1[(size_t)(2 * j) * 128 + n],
                                                  W1[(size_t)(2 * j + 1) * 128 + n]));
        g_wt1[n * ALD + j] = *(uint32_t*)&h;
    } else {
        int t2 = li - 16384;
        if (t2 < 40 * 64) {
            int n = t2 % 40, j = t2 / 40;
            __half2 h = __float22half2_rn(make_float2(W2[(size_t)(2 * j) * CLS + n],
                                                      W2[(size_t)(2 * j + 1) * CLS + n]));
            g_wt2[n * ALD + j] = *(uint32_t*)&h;
        }
    }
}

// ---------------- MMA macro ----------------
#define MMA_H16(d, a, b)                                                     \
    asm volatile(                                                            \
        "mma.sync.aligned.m16n8k16.row.col.f32.f16.f16.f32 "                 \
        "{%0,%1,%2,%3}, {%4,%5,%6,%7}, {%8,%9}, {%0,%1,%2,%3};"              \
        : "+f"(d[0]), "+f"(d[1]), "+f"(d[2]), "+f"(d[3])                     \
        : "r"(a[0]), "r"(a[1]), "r"(a[2]), "r"(a[3]), "r"(b[0]), "r"(b[1]))

#define GEMM_SMEM  ((128 * ALD + 128 * ALD) * 4)   // 69632 B

// ---------------- standalone GEMM0: fp32 features @ W0 -> fp16, rows scaled by norm_out ----
__global__ void __launch_bounds__(256)
gemm0_kernel(const float* __restrict__ A, uint32_t* __restrict__ out, int M) {
    extern __shared__ uint32_t sm[];
    uint32_t* As = sm;
    uint32_t* Ws = sm + 128 * ALD;

    int tid = threadIdx.x, warp = tid >> 5, lane = tid & 31;
    int rowBase = blockIdx.x * 128;

    const uint4* WT = (const uint4*)g_wt0;
#pragma unroll
    for (int it = 0; it < 8; it++) {
        int li = it * 256 + tid;
        int n  = li >> 4;
        int q  = li & 15;
        uint4 v = WT[n * 17 + q];
        uint32_t* p = Ws + n * ALD + q * 4;
        p[0] = v.x; p[1] = v.y; p[2] = v.z; p[3] = v.w;
    }
#pragma unroll
    for (int it = 0; it < 16; it++) {
        int li = it * 256 + tid;
        int r  = li >> 5;
        int c4 = (li & 31) << 2;
        float4 v = make_float4(0.f, 0.f, 0.f, 0.f);
        if (rowBase + r < M)
            v = *(const float4*)(A + (size_t)(rowBase + r) * 128 + c4);
        ((__half2*)As)[r * ALD + (c4 >> 1)]     = __float22half2_rn(make_float2(v.x, v.y));
        ((__half2*)As)[r * ALD + (c4 >> 1) + 1] = __float22half2_rn(make_float2(v.z, v.w));
    }
    __syncthreads();

    int warpRow = warp >> 2, warpCol = warp & 3;
    int gid = lane >> 2, tig = lane & 3;
    int aBase = warpRow * 64, bBase = warpCol * 32;

    float acc[4][4][4];
#pragma unroll
    for (int mf = 0; mf < 4; mf++)
#pragma unroll
        for (int nf = 0; nf < 4; nf++)
#pragma unroll
            for (int q = 0; q < 4; q++) acc[mf][nf][q] = 0.f;

#pragma unroll
    for (int ks = 0; ks < 8; ks++) {
        int kw = ks * 8;
        uint32_t bfr[4][2];
#pragma unroll
        for (int nf = 0; nf < 4; nf++) {
            int n = bBase + nf * 8 + gid;
            bfr[nf][0] = Ws[n * ALD + kw + tig];
            bfr[nf][1] = Ws[n * ALD + kw + 4 + tig];
        }
        uint32_t afr[4][4];
#pragma unroll
        for (int mf = 0; mf < 4; mf++) {
            int r = aBase + mf * 16 + gid;
            afr[mf][0] = As[r * ALD + kw + tig];
            afr[mf][1] = As[(r + 8) * ALD + kw + tig];
            afr[mf][2] = As[r * ALD + kw + 4 + tig];
            afr[mf][3] = As[(r + 8) * ALD + kw + 4 + tig];
        }
#pragma unroll
        for (int mf = 0; mf < 4; mf++)
#pragma unroll
            for (int nf = 0; nf < 4; nf++)
                MMA_H16(acc[mf][nf], afr[mf], bfr[nf]);
    }

#pragma unroll
    for (int mf = 0; mf < 4; mf++) {
        int r0 = rowBase + aBase + mf * 16 + gid;
        int r1 = r0 + 8;
        float s0 = (r0 < M) ? g_norm_out[r0] : 1.f;
        float s1 = (r1 < M) ? g_norm_out[r1] : 1.f;
#pragma unroll
        for (int nf = 0; nf < 4; nf++) {
            int h2col = ((bBase + nf * 8) >> 1) + tig;
            if (r0 < M)
                ((__half2*)out)[(size_t)r0 * 64 + h2col] =
                    __float22half2_rn(make_float2(acc[mf][nf][0] * s0, acc[mf][nf][1] * s0));
            if (r1 < M)
                ((__half2*)out)[(size_t)r1 * 64 + h2col] =
                    __float22half2_rn(make_float2(acc[mf][nf][2] * s1, acc[mf][nf][3] * s1));
        }
    }
}

// ---------------- persistent mega-kernel: agg0 -> gemm1 -> agg1 -> gemm40 -> agg40 ----------

__device__ __forceinline__ void grid_bar(int phase, int nblocks) {
    __syncthreads();
    __threadfence();
    if (threadIdx.x == 0) {
        unsigned v = atomicAdd(&g_bar_arrive, 1u) + 1u;
        if (v == (unsigned)(phase * nblocks)) {
            atomicExch(&g_bar_release, (unsigned)phase);
        } else {
            while (*((volatile unsigned*)&g_bar_release) < (unsigned)phase) {}
        }
        __threadfence();
    }
    __syncthreads();
}

__device__ __forceinline__ void agg_accum(const uint2* __restrict__ tin, int s, int lane,
                                          float& a0, float& a1, float& a2, float& a3) {
    uint2 u = __ldg(&tin[(size_t)s * 32 + lane]);
    float2 p = __half22float2(*(__half2*)&u.x);
    float2 q = __half22float2(*(__half2*)&u.y);
    a0 += p.x; a1 += p.y; a2 += q.x; a3 += q.y;
}

// agg 128 cols: relu + norm_in + bias + norm_out pre-scale; fp16 in/out
__device__ void agg128_stage(const uint2* __restrict__ tin, const float* __restrict__ bias,
                             uint2* __restrict__ outh, int N, int nblocks) {
    int lane = threadIdx.x & 31;
    int warpId = blockIdx.x * 8 + (threadIdx.x >> 5);
    int totalWarps = nblocks * 8;
    float4 b4 = *(const float4*)(bias + lane * 4);

    for (int node = warpId; node < N; node += totalWarps) {
        int beg = g_row_ptr[node];
        int end = g_row_ptr[node + 1];
        float a0 = 0.f, a1 = 0.f, a2 = 0.f, a3 = 0.f;
        int e = beg;
        for (; e + 7 < end; e += 8) {
            agg_accum(tin, g_col[e],     lane, a0, a1, a2, a3);
            agg_accum(tin, g_col[e + 1], lane, a0, a1, a2, a3);
            agg_accum(tin, g_col[e + 2], lane, a0, a1, a2, a3);
            agg_accum(tin, g_col[e + 3], lane, a0, a1, a2, a3);
            agg_accum(tin, g_col[e + 4], lane, a0, a1, a2, a3);
            agg_accum(tin, g_col[e + 5], lane, a0, a1, a2, a3);
            agg_accum(tin, g_col[e + 6], lane, a0, a1, a2, a3);
            agg_accum(tin, g_col[e + 7], lane, a0, a1, a2, a3);
        }
        for (; e < end; e++)
            agg_accum(tin, g_col[e], lane, a0, a1, a2, a3);

        float ni = g_norm_in[node];
        float v0 = fmaxf(a0 * ni + b4.x, 0.f);
        float v1 = fmaxf(a1 * ni + b4.y, 0.f);
        float v2 = fmaxf(a2 * ni + b4.z, 0.f);
        float v3 = fmaxf(a3 * ni + b4.w, 0.f);
        float s = g_norm_out[node];
        v0 *= s; v1 *= s; v2 *= s; v3 *= s;
        uint2 w;
        *(__half2*)&w.x = __float22half2_rn(make_float2(v0, v1));
        *(__half2*)&w.y = __float22half2_rn(make_float2(v2, v3));
        outh[(size_t)node * 32 + lane] = w;
    }
}

// gemm 128 cols: fp16 A (global) @ WT -> fp16 out; tiles looped over persistent blocks
__device__ void gemm128_stage(const uint32_t* __restrict__ Abuf, const uint32_t* __restrict__ WTw,
                              uint32_t* __restrict__ out, int M, int nblocks, uint32_t* sm) {
    uint32_t* As = sm;
    uint32_t* Ws = sm + 128 * ALD;
    int tid = threadIdx.x, warp = tid >> 5, lane = tid & 31;

    const uint4* WT = (const uint4*)WTw;
#pragma unroll
    for (int it = 0; it < 8; it++) {
        int li = it * 256 + tid;
        int n  = li >> 4;
        int q  = li & 15;
        uint4 v = WT[n * 17 + q];
        uint32_t* p = Ws + n * ALD + q * 4;
        p[0] = v.x; p[1] = v.y; p[2] = v.z; p[3] = v.w;
    }

    int warpRow = warp >> 2, warpCol = warp & 3;
    int gid = lane >> 2, tig = lane & 3;
    int aBase = warpRow * 64, bBase = warpCol * 32;
    int nTiles = (M + 127) >> 7;

    const uint4* A = (const uint4*)Abuf;
    for (int tile = blockIdx.x; tile < nTiles; tile += nblocks) {
        int rowBase = tile * 128;
        __syncthreads();   // As safe to overwrite (covers Ws readiness on first iter)
#pragma unroll
        for (int it = 0; it < 8; it++) {
            int li = it * 256 + tid;
            int r  = li >> 4;
            int w4 = (li & 15) << 2;
            uint4 v = make_uint4(0u, 0u, 0u, 0u);
            if (rowBase + r < M)
                v = A[(size_t)(rowBase + r) * 16 + (w4 >> 2)];
            As[r * ALD + w4]     = v.x;
            As[r * ALD + w4 + 1] = v.y;
            As[r * ALD + w4 + 2] = v.z;
            As[r * ALD + w4 + 3] = v.w;
        }
        __syncthreads();

        float acc[4][4][4];
#pragma unroll
        for (int mf = 0; mf < 4; mf++)
#pragma unroll
            for (int nf = 0; nf < 4; nf++)
#pragma unroll
                for (int q = 0; q < 4; q++) acc[mf][nf][q] = 0.f;

#pragma unroll
        for (int ks = 0; ks < 8; ks++) {
            int kw = ks * 8;
            uint32_t bfr[4][2];
#pragma unroll
            for (int nf = 0; nf < 4; nf++) {
                int n = bBase + nf * 8 + gid;
                bfr[nf][0] = Ws[n * ALD + kw + tig];
                bfr[nf][1] = Ws[n * ALD + kw + 4 + tig];
            }
            uint32_t afr[4][4];
#pragma unroll
            for (int mf = 0; mf < 4; mf++) {
                int r = aBase + mf * 16 + gid;
                afr[mf][0] = As[r * ALD + kw + tig];
                afr[mf][1] = As[(r + 8) * ALD + kw + tig];
                afr[mf][2] = As[r * ALD + kw + 4 + tig];
                afr[mf][3] = As[(r + 8) * ALD + kw + 4 + tig];
            }
#pragma unroll
            for (int mf = 0; mf < 4; mf++)
#pragma unroll
                for (int nf = 0; nf < 4; nf++)
                    MMA_H16(acc[mf][nf], afr[mf], bfr[nf]);
        }

#pragma unroll
        for (int mf = 0; mf < 4; mf++) {
            int r0 = rowBase + aBase + mf * 16 + gid;
            int r1 = r0 + 8;
#pragma unroll
            for (int nf = 0; nf < 4; nf++) {
                int h2col = ((bBase + nf * 8) >> 1) + tig;
                if (r0 < M)
                    ((__half2*)out)[(size_t)r0 * 64 + h2col] =
                        __float22half2_rn(make_float2(acc[mf][nf][0], acc[mf][nf][1]));
                if (r1 < M)
                    ((__half2*)out)[(size_t)r1 * 64 + h2col] =
                        __float22half2_rn(make_float2(acc[mf][nf][2], acc[mf][nf][3]));
            }
        }
    }
}

// gemm 40 cols: fp16 A @ W2 -> fp16 out (20 words/row)
__device__ void gemm40_stage(const uint32_t* __restrict__ Abuf, const uint32_t* __restrict__ WTw,
                             uint32_t* __restrict__ out, int M, int nblocks, uint32_t* sm) {
    uint32_t* As = sm;
    uint32_t* Ws = sm + 128 * ALD;
    int tid = threadIdx.x, warp = tid >> 5, lane = tid & 31;

    const uint4* WT = (const uint4*)WTw;
#pragma unroll
    for (int it = 0; it < 3; it++) {
        int li = it * 256 + tid;
        if (li < 640) {
            int n = li >> 4;
            int q = li & 15;
            uint4 v = WT[n * 17 + q];
            uint32_t* p = Ws + n * ALD + q * 4;
            p[0] = v.x; p[1] = v.y; p[2] = v.z; p[3] = v.w;
        }
    }

    int gid = lane >> 2, tig = lane & 3;
    int aBase = warp * 16;
    int nTiles = (M + 127) >> 7;

    const uint4* A = (const uint4*)Abuf;
    for (int tile = blockIdx.x; tile < nTiles; tile += nblocks) {
        int rowBase = tile * 128;
        __syncthreads();
#pragma unroll
        for (int it = 0; it < 8; it++) {
            int li = it * 256 + tid;
            int r  = li >> 4;
            int w4 = (li & 15) << 2;
            uint4 v = make_uint4(0u, 0u, 0u, 0u);
            if (rowBase + r < M)
                v = A[(size_t)(rowBase + r) * 16 + (w4 >> 2)];
            As[r * ALD + w4]     = v.x;
            As[r * ALD + w4 + 1] = v.y;
            As[r * ALD + w4 + 2] = v.z;
            As[r * ALD + w4 + 3] = v.w;
        }
        __syncthreads();

        float acc[5][4];
#pragma unroll
        for (int nf = 0; nf < 5; nf++)
#pragma unroll
            for (int q = 0; q < 4; q++) acc[nf][q] = 0.f;

#pragma unroll
        for (int ks = 0; ks < 8; ks++) {
            int kw = ks * 8;
            uint32_t afr[4];
            {
                int r = aBase + gid;
                afr[0] = As[r * ALD + kw + tig];
                afr[1] = As[(r + 8) * ALD + kw + tig];
                afr[2] = As[r * ALD + kw + 4 + tig];
                afr[3] = As[(r + 8) * ALD + kw + 4 + tig];
            }
#pragma unroll
            for (int nf = 0; nf < 5; nf++) {
                int n = nf * 8 + gid;
                uint32_t bfr[2];
                bfr[0] = Ws[n * ALD + kw + tig];
                bfr[1] = Ws[n * ALD + kw + 4 + tig];
                MMA_H16(acc[nf], afr, bfr);
            }
        }

        int r0 = rowBase + aBase + gid;
        int r1 = r0 + 8;
#pragma unroll
        for (int nf = 0; nf < 5; nf++) {
            int h2col = nf * 4 + tig;
            if (r0 < M)
                ((__half2*)out)[(size_t)r0 * 20 + h2col] =
                    __float22half2_rn(make_float2(acc[nf][0], acc[nf][1]));
            if (r1 < M)
                ((__half2*)out)[(size_t)r1 * 20 + h2col] =
                    __float22half2_rn(make_float2(acc[nf][2], acc[nf][3]));
        }
    }
}

// agg 40 cols: fp16 in, fp32 out + bias + norm_in
__device__ void agg40_stage(const uint32_t* __restrict__ tin, const float* __restrict__ bias,
                            float* __restrict__ out, int N, int nblocks) {
    int lane = threadIdx.x & 31;
    int warpId = blockIdx.x * 8 + (threadIdx.x >> 5);
    int totalWarps = nblocks * 8;
    if (lane >= 20) return;
    float2 b2 = *(const float2*)(bias + lane * 2);

    for (int node = warpId; node < N; node += totalWarps) {
        int beg = g_row_ptr[node];
        int end = g_row_ptr[node + 1];
        float ax = 0.f, ay = 0.f;
        for (int e = beg; e < end; e++) {
            uint32_t u = __ldg(&tin[(size_t)g_col[e] * 20 + lane]);
            float2 f = __half22float2(*(__half2*)&u);
            ax += f.x; ay += f.y;
        }
        float ni = g_norm_in[node];
        *(float2*)(out + (size_t)node * CLS + lane * 2) =
            make_float2(ax * ni + b2.x, ay * ni + b2.y);
    }
}

__global__ void __launch_bounds__(256, 2)
layers_kernel(const float* __restrict__ b0, const float* __restrict__ b1,
              const float* __restrict__ b2, float* __restrict__ out,
              int N, int nblocks) {
    extern __shared__ uint32_t sm[];

    // stage A: agg0  buf_a -> buf_b
    agg128_stage((const uint2*)g_buf_a, b0, (uint2*)g_buf_b, N, nblocks);
    grid_bar(1, nblocks);
    // stage B: gemm1  buf_b -> buf_a
    gemm128_stage(g_buf_b, g_wt1, g_buf_a, N, nblocks, sm);
    grid_bar(2, nblocks);
    // stage C: agg1  buf_a -> buf_b
    agg128_stage((const uint2*)g_buf_a, b1, (uint2*)g_buf_b, N, nblocks);
    grid_bar(3, nblocks);
    // stage D: gemm40  buf_b -> buf_a
    gemm40_stage(g_buf_b, g_wt2, g_buf_a, N, nblocks, sm);
    grid_bar(4, nblocks);
    // stage E: agg40  buf_a -> out
    agg40_stage(g_buf_a, b2, out, N, nblocks);
}

// ---------------- host launcher ----------------
extern "C" void kernel_launch(void* const* d_in, const int* in_sizes, int n_in,
                              void* d_out, int out_size) {
    const float* features = (const float*)d_in[0];
    const int*   src      = (const int*)d_in[1];
    const int*   dst      = (const int*)d_in[2];
    const float* W0       = (const float*)d_in[3];
    const float* b0       = (const float*)d_in[4];
    const float* W1       = (const float*)d_in[5];
    const float* b1       = (const float*)d_in[6];
    const float* W2       = (const float*)d_in[7];
    const float* b2       = (const float*)d_in[8];
    float* out = (float*)d_out;

    int N = in_sizes[0] / KDIM;   // 50000
    int E = in_sizes[1];          // 800000

    static cudaStream_t s_pre = nullptr;
    static cudaEvent_t ev_fork = nullptr, ev_norm = nullptr, ev_join = nullptr;
    static void *p_buf_a = nullptr;
    static int smCount = 0;
    if (!s_pre) {
        cudaStreamCreateWithFlags(&s_pre, cudaStreamNonBlocking);
        cudaEventCreateWithFlags(&ev_fork, cudaEventDisableTiming);
        cudaEventCreateWithFlags(&ev_norm, cudaEventDisableTiming);
        cudaEventCreateWithFlags(&ev_join, cudaEventDisableTiming);
        cudaGetSymbolAddress(&p_buf_a, g_buf_a);
        cudaDeviceGetAttribute(&smCount, cudaDevAttrMultiProcessorCount, 0);
        cudaFuncSetAttribute(gemm0_kernel,
                             cudaFuncAttributeMaxDynamicSharedMemorySize, GEMM_SMEM);
        cudaFuncSetAttribute(layers_kernel,
                             cudaFuncAttributeMaxDynamicSharedMemorySize, GEMM_SMEM);
    }

    int nScanBlocks = (N + 255) / 256;   // 196
    int gemmGrid = (N + 127) / 128;      // 391
    int persBlocks = 2 * smCount;        // exactly 2 blocks/SM co-resident

    // ---- fork: pre-chain on s_pre; wconv + gemm0 on main ----
    cudaEventRecord(ev_fork, 0);
    cudaStreamWaitEvent(s_pre, ev_fork, 0);

    init_zero_kernel<<<196, 256, 0, s_pre>>>(N);
    degree_kernel<<<(E + 255) / 256, 256, 0, s_pre>>>(src, dst, E);
    norm_partial_kernel<<<nScanBlocks, 256, 0, s_pre>>>(N);
    cudaEventRecord(ev_norm, s_pre);

    wconvert_all_kernel<<<74, 256>>>(W0, W1, W2);

    cudaStreamWaitEvent(0, ev_norm, 0);
    gemm0_kernel<<<gemmGrid, 256, GEMM_SMEM>>>(features, (uint32_t*)p_buf_a, N);

    fill_rowptr_kernel<<<nScanBlocks, 256, 0, s_pre>>>(nScanBlocks, N);
    csr_fill_kernel<<<(E + 255) / 256, 256, 0, s_pre>>>(src, dst, E);
    cudaEventRecord(ev_join, s_pre);
    cudaStreamWaitEvent(0, ev_join, 0);

    // ---- fused layers: agg0 -> gemm1 -> agg1 -> gemm40 -> agg40 ----
    layers_kernel<<<persBlocks, 256, GEMM_SMEM>>>(b0, b1, b2, out, N, persBlocks);
}

// round 15
// speedup vs baseline: 1.3143x; 1.3143x over previous
#include <cuda_runtime.h>
#include <cuda_fp16.h>
#include <math.h>
#include <stdint.h>

#define NN 50000
#define EE 800000
#define KDIM 128
#define HID 128
#define CLS 40

#define ALD 68   // half2-words per smem row (64 data + 4 pad) -> conflict-free MMA frag loads

// ---------------- scratch (device globals; no allocation allowed) ----------------
__device__ int   g_deg_out[NN];
__device__ int   g_deg_in[NN];
__device__ int   g_cursor[NN];
__device__ int   g_row_ptr[NN + 1];
__device__ int   g_col[EE];
__device__ float g_norm_out[NN];
__device__ float g_norm_in[NN];
__device__ int   g_block_sums[256];
__device__ __align__(16) uint32_t g_wt0[128 * ALD];
__device__ __align__(16) uint32_t g_wt1[128 * ALD];
__device__ __align__(16) uint32_t g_wt2[40 * ALD];
__device__ __align__(16) uint32_t g_buf_a[(size_t)NN * 64];   // fp16, 64 words/row
__device__ __align__(16) uint32_t g_buf_b[(size_t)NN * 64];

// ---------------- graph preprocessing ----------------
__global__ void init_zero_kernel(int n) {
    for (int i = blockIdx.x * blockDim.x + threadIdx.x; i < n; i += gridDim.x * blockDim.x) {
        g_deg_out[i] = 0;
        g_deg_in[i]  = 0;
    }
}

__global__ void degree_kernel(const int* __restrict__ src, const int* __restrict__ dst, int E) {
    int e = blockIdx.x * blockDim.x + threadIdx.x;
    if (e < E) {
        atomicAdd(&g_deg_out[src[e]], 1);
        atomicAdd(&g_deg_in[dst[e]], 1);
    }
}

// fused: per-node norms + per-block partial sums of deg_in
__global__ void norm_partial_kernel(int n) {
    __shared__ int sdata[8];
    int t = threadIdx.x;
    int i = blockIdx.x * 256 + t;
    int din = 0;
    if (i < n) {
        int dout = g_deg_out[i]; if (dout < 1) dout = 1;
        din = g_deg_in[i];
        int dc = (din < 1) ? 1 : din;
        g_norm_out[i] = rsqrtf((float)dout);
        g_norm_in[i]  = rsqrtf((float)dc);
    }
    int v = din;
    for (int off = 16; off > 0; off >>= 1)
        v += __shfl_down_sync(0xffffffff, v, off);
    if ((t & 31) == 0) sdata[t >> 5] = v;
    __syncthreads();
    if (t < 8) {
        int w = sdata[t];
        for (int off = 4; off > 0; off >>= 1)
            w += __shfl_down_sync(0xff, w, off);
        if (t == 0) g_block_sums[blockIdx.x] = w;
    }
}

// fill row_ptr + cursor; each block redundantly scans the <=256 block partials
__global__ void fill_rowptr_kernel(int nblocks, int n) {
    __shared__ int sg[256];
    __shared__ int sl[256];
    int t = threadIdx.x;
    int v = (t < nblocks) ? g_block_sums[t] : 0;
    sg[t] = v;
    __syncthreads();
    for (int off = 1; off < 256; off <<= 1) {
        int u = (t >= off) ? sg[t - off] : 0;
        __syncthreads();
        sg[t] += u;
        __syncthreads();
    }
    int blockOff = (blockIdx.x == 0) ? 0 : sg[blockIdx.x - 1];
    if (blockIdx.x == 0 && t == 0) g_row_ptr[n] = sg[nblocks - 1];
    int i = blockIdx.x * 256 + t;
    int d = (i < n) ? g_deg_in[i] : 0;
    sl[t] = d;
    __syncthreads();
    for (int off = 1; off < 256; off <<= 1) {
        int u = (t >= off) ? sl[t - off] : 0;
        __syncthreads();
        sl[t] += u;
        __syncthreads();
    }
    if (i < n) {
        int rp = sl[t] - d + blockOff;
        g_row_ptr[i] = rp;
        g_cursor[i]  = rp;
    }
}

__global__ void csr_fill_kernel(const int* __restrict__ src, const int* __restrict__ dst, int E) {
    int e = blockIdx.x * blockDim.x + threadIdx.x;
    if (e < E) {
        int p = atomicAdd(&g_cursor[dst[e]], 1);
        g_col[p] = src[e];
    }
}

// ---------------- fused weight pre-conversion (all three) ----------------
__global__ void wconvert_all_kernel(const float* __restrict__ W0, const float* __restrict__ W1,
                                    const float* __restrict__ W2) {
    int li = blockIdx.x * 256 + threadIdx.x;
    if (li < 8192) {
        int n = li & 127, j = li >> 7;
        __half2 h = __float22half2_rn(make_float2(W0[(size_t)(2 * j) * 128 + n],
                                                  W0[(size_t)(2 * j + 1) * 128 + n]));
        g_wt0[n * ALD + j] = *(uint32_t*)&h;
    } else if (li < 16384) {
        int t2 = li - 8192;
        int n = t2 & 127, j = t2 >> 7;
        __half2 h = __float22half2_rn(make_float2(W1[(size_t)(2 * j) * 128 + n],
                                                  W1[(size_t)(2 * j + 1) * 128 + n]));
        g_wt1[n * ALD + j] = *(uint32_t*)&h;
    } else {
        int t2 = li - 16384;
        if (t2 < 40 * 64) {
            int n = t2 % 40, j = t2 / 40;
            __half2 h = __float22half2_rn(make_float2(W2[(size_t)(2 * j) * CLS + n],
                                                      W2[(size_t)(2 * j + 1) * CLS + n]));
            g_wt2[n * ALD + j] = *(uint32_t*)&h;
        }
    }
}

// ---------------- MMA macro ----------------
#define MMA_H16(d, a, b)                                                     \
    asm volatile(                                                            \
        "mma.sync.aligned.m16n8k16.row.col.f32.f16.f16.f32 "                 \
        "{%0,%1,%2,%3}, {%4,%5,%6,%7}, {%8,%9}, {%0,%1,%2,%3};"              \
        : "+f"(d[0]), "+f"(d[1]), "+f"(d[2]), "+f"(d[3])                     \
        : "r"(a[0]), "r"(a[1]), "r"(a[2]), "r"(a[3]), "r"(b[0]), "r"(b[1]))

#define GEMM_SMEM  ((128 * ALD + 128 * ALD) * 4)
#define GEMM40_SMEM ((128 * ALD + 40 * ALD) * 4)

// ---------------- GEMM 128 out cols ----------------
template <int AF32, int SCALEOUT>
__global__ void __launch_bounds__(256)
gemm128_h16(const void* __restrict__ Ain, const uint4* __restrict__ WT,
            uint32_t* __restrict__ out, int M) {
    extern __shared__ uint32_t sm[];
    uint32_t* As = sm;
    uint32_t* Ws = sm + 128 * ALD;

    int tid = threadIdx.x, warp = tid >> 5, lane = tid & 31;
    int rowBase = blockIdx.x * 128;

#pragma unroll
    for (int it = 0; it < 8; it++) {
        int li = it * 256 + tid;
        int n  = li >> 4;
        int q  = li & 15;
        uint4 v = WT[n * 17 + q];
        uint32_t* p = Ws + n * ALD + q * 4;
        p[0] = v.x; p[1] = v.y; p[2] = v.z; p[3] = v.w;
    }

    if (AF32) {
        const float* A = (const float*)Ain;
#pragma unroll
        for (int it = 0; it < 16; it++) {
            int li = it * 256 + tid;
            int r  = li >> 5;
            int c4 = (li & 31) << 2;
            float4 v = make_float4(0.f, 0.f, 0.f, 0.f);
            if (rowBase + r < M)
                v = *(const float4*)(A + (size_t)(rowBase + r) * 128 + c4);
            ((__half2*)As)[r * ALD + (c4 >> 1)]     = __float22half2_rn(make_float2(v.x, v.y));
            ((__half2*)As)[r * ALD + (c4 >> 1) + 1] = __float22half2_rn(make_float2(v.z, v.w));
        }
    } else {
        const uint4* A = (const uint4*)Ain;
#pragma unroll
        for (int it = 0; it < 8; it++) {
            int li = it * 256 + tid;
            int r  = li >> 4;
            int w4 = (li & 15) << 2;
            uint4 v = make_uint4(0u, 0u, 0u, 0u);
            if (rowBase + r < M)
                v = A[(size_t)(rowBase + r) * 16 + (w4 >> 2)];
            As[r * ALD + w4]     = v.x;
            As[r * ALD + w4 + 1] = v.y;
            As[r * ALD + w4 + 2] = v.z;
            As[r * ALD + w4 + 3] = v.w;
        }
    }
    __syncthreads();

    int warpRow = warp >> 2, warpCol = warp & 3;
    int gid = lane >> 2, tig = lane & 3;
    int aBase = warpRow * 64, bBase = warpCol * 32;

    float acc[4][4][4];
#pragma unroll
    for (int mf = 0; mf < 4; mf++)
#pragma unroll
        for (int nf = 0; nf < 4; nf++)
#pragma unroll
            for (int q = 0; q < 4; q++) acc[mf][nf][q] = 0.f;

#pragma unroll
    for (int ks = 0; ks < 8; ks++) {
        int kw = ks * 8;
        uint32_t bfr[4][2];
#pragma unroll
        for (int nf = 0; nf < 4; nf++) {
            int n = bBase + nf * 8 + gid;
            bfr[nf][0] = Ws[n * ALD + kw + tig];
            bfr[nf][1] = Ws[n * ALD + kw + 4 + tig];
        }
        uint32_t afr[4][4];
#pragma unroll
        for (int mf = 0; mf < 4; mf++) {
            int r = aBase + mf * 16 + gid;
            afr[mf][0] = As[r * ALD + kw + tig];
            afr[mf][1] = As[(r + 8) * ALD + kw + tig];
            afr[mf][2] = As[r * ALD + kw + 4 + tig];
            afr[mf][3] = As[(r + 8) * ALD + kw + 4 + tig];
        }
#pragma unroll
        for (int mf = 0; mf < 4; mf++)
#pragma unroll
            for (int nf = 0; nf < 4; nf++)
                MMA_H16(acc[mf][nf], afr[mf], bfr[nf]);
    }

#pragma unroll
    for (int mf = 0; mf < 4; mf++) {
        int r0 = rowBase + aBase + mf * 16 + gid;
        int r1 = r0 + 8;
        float s0 = 1.f, s1 = 1.f;
        if (SCALEOUT) {
            if (r0 < M) s0 = g_norm_out[r0];
            if (r1 < M) s1 = g_norm_out[r1];
        }
#pragma unroll
        for (int nf = 0; nf < 4; nf++) {
            int h2col = ((bBase + nf * 8) >> 1) + tig;
            if (r0 < M)
                ((__half2*)out)[(size_t)r0 * 64 + h2col] =
                    __float22half2_rn(make_float2(acc[mf][nf][0] * s0, acc[mf][nf][1] * s0));
            if (r1 < M)
                ((__half2*)out)[(size_t)r1 * 64 + h2col] =
                    __float22half2_rn(make_float2(acc[mf][nf][2] * s1, acc[mf][nf][3] * s1));
        }
    }
}

// ---------------- GEMM 40 out cols ----------------
__global__ void __launch_bounds__(256)
gemm40_h16(const void* __restrict__ Ain, const uint4* __restrict__ WT,
           uint32_t* __restrict__ out, int M) {
    extern __shared__ uint32_t sm[];
    uint32_t* As = sm;
    uint32_t* Ws = sm + 128 * ALD;

    int tid = threadIdx.x, warp = tid >> 5, lane = tid & 31;
    int rowBase = blockIdx.x * 128;

#pragma unroll
    for (int it = 0; it < 3; it++) {
        int li = it * 256 + tid;
        if (li < 640) {
            int n = li >> 4;
            int q = li & 15;
            uint4 v = WT[n * 17 + q];
            uint32_t* p = Ws + n * ALD + q * 4;
            p[0] = v.x; p[1] = v.y; p[2] = v.z; p[3] = v.w;
        }
    }

    const uint4* A = (const uint4*)Ain;
#pragma unroll
    for (int it = 0; it < 8; it++) {
        int li = it * 256 + tid;
        int r  = li >> 4;
        int w4 = (li & 15) << 2;
        uint4 v = make_uint4(0u, 0u, 0u, 0u);
        if (rowBase + r < M)
            v = A[(size_t)(rowBase + r) * 16 + (w4 >> 2)];
        As[r * ALD + w4]     = v.x;
        As[r * ALD + w4 + 1] = v.y;
        As[r * ALD + w4 + 2] = v.z;
        As[r * ALD + w4 + 3] = v.w;
    }
    __syncthreads();

    int gid = lane >> 2, tig = lane & 3;
    int aBase = warp * 16;

    float acc[5][4];
#pragma unroll
    for (int nf = 0; nf < 5; nf++)
#pragma unroll
        for (int q = 0; q < 4; q++) acc[nf][q] = 0.f;

#pragma unroll
    for (int ks = 0; ks < 8; ks++) {
        int kw = ks * 8;
        uint32_t afr[4];
        {
            int r = aBase + gid;
            afr[0] = As[r * ALD + kw + tig];
            afr[1] = As[(r + 8) * ALD + kw + tig];
            afr[2] = As[r * ALD + kw + 4 + tig];
            afr[3] = As[(r + 8) * ALD + kw + 4 + tig];
        }
#pragma unroll
        for (int nf = 0; nf < 5; nf++) {
            int n = nf * 8 + gid;
            uint32_t bfr[2];
            bfr[0] = Ws[n * ALD + kw + tig];
            bfr[1] = Ws[n * ALD + kw + 4 + tig];
            MMA_H16(acc[nf], afr, bfr);
        }
    }

    int r0 = rowBase + aBase + gid;
    int r1 = r0 + 8;
#pragma unroll
    for (int nf = 0; nf < 5; nf++) {
        int h2col = nf * 4 + tig;
        if (r0 < M)
            ((__half2*)out)[(size_t)r0 * 20 + h2col] =
                __float22half2_rn(make_float2(acc[nf][0], acc[nf][1]));
        if (r1 < M)
            ((__half2*)out)[(size_t)r1 * 20 + h2col] =
                __float22half2_rn(make_float2(acc[nf][2], acc[nf][3]));
    }
}

// ---------------- aggregation (128 cols, fp16 in/out), warp-per-node, high occupancy ----
#define AGG_BLOCKS 1184   // 8 blocks/SM submitted; regs-limited residency ~6/SM -> ~48 warps/SM

__device__ __forceinline__ void agg_accum(const uint2* __restrict__ tin, int s, int lane,
                                          float& a0, float& a1, float& a2, float& a3) {
    uint2 u = __ldg(&tin[(size_t)s * 32 + lane]);
    float2 p = __half22float2(*(__half2*)&u.x);
    float2 q = __half22float2(*(__half2*)&u.y);
    a0 += p.x; a1 += p.y; a2 += q.x; a3 += q.y;
}

__global__ void __launch_bounds__(256)
agg_f16_kernel(const uint2* __restrict__ tin, const float* __restrict__ bias,
               uint2* __restrict__ outh, int N) {
    int lane = threadIdx.x & 31;
    int warpId = blockIdx.x * 8 + (threadIdx.x >> 5);
    int totalWarps = gridDim.x * 8;
    float4 b4 = *(const float4*)(bias + lane * 4);

    for (int node = warpId; node < N; node += totalWarps) {
        int beg = g_row_ptr[node];
        int end = g_row_ptr[node + 1];
        float a0 = 0.f, a1 = 0.f, a2 = 0.f, a3 = 0.f;
        int e = beg;
        for (; e + 7 < end; e += 8) {
            agg_accum(tin, g_col[e],     lane, a0, a1, a2, a3);
            agg_accum(tin, g_col[e + 1], lane, a0, a1, a2, a3);
            agg_accum(tin, g_col[e + 2], lane, a0, a1, a2, a3);
            agg_accum(tin, g_col[e + 3], lane, a0, a1, a2, a3);
            agg_accum(tin, g_col[e + 4], lane, a0, a1, a2, a3);
            agg_accum(tin, g_col[e + 5], lane, a0, a1, a2, a3);
            agg_accum(tin, g_col[e + 6], lane, a0, a1, a2, a3);
            agg_accum(tin, g_col[e + 7], lane, a0, a1, a2, a3);
        }
        for (; e + 3 < end; e += 4) {
            agg_accum(tin, g_col[e],     lane, a0, a1, a2, a3);
            agg_accum(tin, g_col[e + 1], lane, a0, a1, a2, a3);
            agg_accum(tin, g_col[e + 2], lane, a0, a1, a2, a3);
            agg_accum(tin, g_col[e + 3], lane, a0, a1, a2, a3);
        }
        for (; e < end; e++)
            agg_accum(tin, g_col[e], lane, a0, a1, a2, a3);

        float ni = g_norm_in[node];
        float v0 = fmaxf(a0 * ni + b4.x, 0.f);
        float v1 = fmaxf(a1 * ni + b4.y, 0.f);
        float v2 = fmaxf(a2 * ni + b4.z, 0.f);
        float v3 = fmaxf(a3 * ni + b4.w, 0.f);
        float s = g_norm_out[node];
        v0 *= s; v1 *= s; v2 *= s; v3 *= s;
        uint2 w;
        *(__half2*)&w.x = __float22half2_rn(make_float2(v0, v1));
        *(__half2*)&w.y = __float22half2_rn(make_float2(v2, v3));
        outh[(size_t)node * 32 + lane] = w;
    }
}

// ---------------- final aggregation (40 cols, fp16 in, fp32 out) ----------------
__device__ __forceinline__ void agg40_accum(const uint32_t* __restrict__ tin, int s, int lane,
                                            float& ax, float& ay) {
    uint32_t u = __ldg(&tin[(size_t)s * 20 + lane]);
    float2 f = __half22float2(*(__half2*)&u);
    ax += f.x; ay += f.y;
}

__global__ void __launch_bounds__(256)
agg40_kernel(const uint32_t* __restrict__ tin, const float* __restrict__ bias,
             float* __restrict__ out, int N) {
    int lane = threadIdx.x & 31;
    int warpId = blockIdx.x * 8 + (threadIdx.x >> 5);
    int totalWarps = gridDim.x * 8;
    if (lane >= 20) return;
    float2 b2 = *(const float2*)(bias + lane * 2);

    for (int node = warpId; node < N; node += totalWarps) {
        int beg = g_row_ptr[node];
        int end = g_row_ptr[node + 1];
        float ax = 0.f, ay = 0.f;
        int e = beg;
        for (; e + 7 < end; e += 8) {
            agg40_accum(tin, g_col[e],     lane, ax, ay);
            agg40_accum(tin, g_col[e + 1], lane, ax, ay);
            agg40_accum(tin, g_col[e + 2], lane, ax, ay);
            agg40_accum(tin, g_col[e + 3], lane, ax, ay);
            agg40_accum(tin, g_col[e + 4], lane, ax, ay);
            agg40_accum(tin, g_col[e + 5], lane, ax, ay);
            agg40_accum(tin, g_col[e + 6], lane, ax, ay);
            agg40_accum(tin, g_col[e + 7], lane, ax, ay);
        }
        for (; e + 3 < end; e += 4) {
            agg40_accum(tin, g_col[e],     lane, ax, ay);
            agg40_accum(tin, g_col[e + 1], lane, ax, ay);
            agg40_accum(tin, g_col[e + 2], lane, ax, ay);
            agg40_accum(tin, g_col[e + 3], lane, ax, ay);
        }
        for (; e < end; e++)
            agg40_accum(tin, g_col[e], lane, ax, ay);

        float ni = g_norm_in[node];
        *(float2*)(out + (size_t)node * CLS + lane * 2) =
            make_float2(ax * ni + b2.x, ay * ni + b2.y);
    }
}

// ---------------- host launcher ----------------
extern "C" void kernel_launch(void* const* d_in, const int* in_sizes, int n_in,
                              void* d_out, int out_size) {
    const float* features = (const float*)d_in[0];
    const int*   src      = (const int*)d_in[1];
    const int*   dst      = (const int*)d_in[2];
    const float* W0       = (const float*)d_in[3];
    const float* b0       = (const float*)d_in[4];
    const float* W1       = (const float*)d_in[5];
    const float* b1       = (const float*)d_in[6];
    const float* W2       = (const float*)d_in[7];
    const float* b2       = (const float*)d_in[8];
    float* out = (float*)d_out;

    int N = in_sizes[0] / KDIM;   // 50000
    int E = in_sizes[1];          // 800000

    static cudaStream_t s_pre = nullptr;
    static cudaEvent_t ev_fork = nullptr, ev_norm = nullptr, ev_join = nullptr;
    static void *p_buf_a = nullptr, *p_buf_b = nullptr;
    static void *p_wt0 = nullptr, *p_wt1 = nullptr, *p_wt2 = nullptr;
    if (!s_pre) {
        cudaStreamCreateWithFlags(&s_pre, cudaStreamNonBlocking);
        cudaEventCreateWithFlags(&ev_fork, cudaEventDisableTiming);
        cudaEventCreateWithFlags(&ev_norm, cudaEventDisableTiming);
        cudaEventCreateWithFlags(&ev_join, cudaEventDisableTiming);
        cudaGetSymbolAddress(&p_buf_a, g_buf_a);
        cudaGetSymbolAddress(&p_buf_b, g_buf_b);
        cudaGetSymbolAddress(&p_wt0, g_wt0);
        cudaGetSymbolAddress(&p_wt1, g_wt1);
        cudaGetSymbolAddress(&p_wt2, g_wt2);
        cudaFuncSetAttribute(gemm128_h16<1, 1>,
                             cudaFuncAttributeMaxDynamicSharedMemorySize, GEMM_SMEM);
        cudaFuncSetAttribute(gemm128_h16<0, 0>,
                             cudaFuncAttributeMaxDynamicSharedMemorySize, GEMM_SMEM);
        cudaFuncSetAttribute(gemm40_h16,
                             cudaFuncAttributeMaxDynamicSharedMemorySize, GEMM40_SMEM);
    }

    int nScanBlocks = (N + 255) / 256;   // 196
    int gemmGrid = (N + 127) / 128;      // 391

    // ---- fork: pre-chain on s_pre; wconv + gemm0 on main ----
    cudaEventRecord(ev_fork, 0);
    cudaStreamWaitEvent(s_pre, ev_fork, 0);

    init_zero_kernel<<<196, 256, 0, s_pre>>>(N);
    degree_kernel<<<(E + 255) / 256, 256, 0, s_pre>>>(src, dst, E);
    norm_partial_kernel<<<nScanBlocks, 256, 0, s_pre>>>(N);
    cudaEventRecord(ev_norm, s_pre);

    wconvert_all_kernel<<<74, 256>>>(W0, W1, W2);

    cudaStreamWaitEvent(0, ev_norm, 0);
    gemm128_h16<1, 1><<<gemmGrid, 256, GEMM_SMEM>>>(features, (const uint4*)p_wt0,
                                                    (uint32_t*)p_buf_a, N);

    fill_rowptr_kernel<<<nScanBlocks, 256, 0, s_pre>>>(nScanBlocks, N);
    csr_fill_kernel<<<(E + 255) / 256, 256, 0, s_pre>>>(src, dst, E);
    cudaEventRecord(ev_join, s_pre);
    cudaStreamWaitEvent(0, ev_join, 0);

    // layer 0 agg -> fp16 h (relu, norm_in, pre-scaled by norm_out)
    agg_f16_kernel<<<AGG_BLOCKS, 256>>>((const uint2*)p_buf_a, b0, (uint2*)p_buf_b, N);
    // layer 1
    gemm128_h16<0, 0><<<gemmGrid, 256, GEMM_SMEM>>>(p_buf_b, (const uint4*)p_wt1,
                                                    (uint32_t*)p_buf_a, N);
    agg_f16_kernel<<<AGG_BLOCKS, 256>>>((const uint2*)p_buf_a, b1, (uint2*)p_buf_b, N);
    // layer 2 (40 classes)
    gemm40_h16<<<gemmGrid, 256, GEMM40_SMEM>>>(p_buf_b, (const uint4*)p_wt2,
                                               (uint32_t*)p_buf_a, N);
    agg40_kernel<<<AGG_BLOCKS, 256>>>((const uint32_t*)p_buf_a, b2, out, N);
}